// round 1
// baseline (speedup 1.0000x reference)
#include <cuda_runtime.h>

// PostProcessingBlock: 50 iterations of a NOTEARS-style augmented-Lagrangian
// step on 512 independent 64x64 adjacency matrices.
// One CTA per batch element; all state lives in shared memory.

#define NMAT   64
#define LDM    68                 // padded row stride (floats): avoids LDS bank conflicts, keeps float4 alignment
#define MATF   (NMAT * LDM)       // floats per matrix buffer
#define NTH    256

// C = A @ B, 64x64x64 fp32, operands in shared memory (row stride LDM).
// 256 threads, each computes a 4x4 output tile. Caller handles barriers.
__device__ __forceinline__ void mm64(float* __restrict__ C,
                                     const float* __restrict__ A,
                                     const float* __restrict__ B,
                                     int tid)
{
    const int tx = (tid & 15) * 4;   // output column base
    const int ty = (tid >> 4) * 4;   // output row base

    const float* a0 = A + (ty + 0) * LDM;
    const float* a1 = A + (ty + 1) * LDM;
    const float* a2 = A + (ty + 2) * LDM;
    const float* a3 = A + (ty + 3) * LDM;
    const float* bp = B + tx;

    float acc[4][4];
#pragma unroll
    for (int r = 0; r < 4; r++)
#pragma unroll
        for (int c = 0; c < 4; c++)
            acc[r][c] = 0.0f;

#pragma unroll 8
    for (int k = 0; k < NMAT; k++) {
        const float4 b = *reinterpret_cast<const float4*>(bp + k * LDM);
        const float v0 = a0[k];
        const float v1 = a1[k];
        const float v2 = a2[k];
        const float v3 = a3[k];

        acc[0][0] = fmaf(v0, b.x, acc[0][0]);
        acc[0][1] = fmaf(v0, b.y, acc[0][1]);
        acc[0][2] = fmaf(v0, b.z, acc[0][2]);
        acc[0][3] = fmaf(v0, b.w, acc[0][3]);

        acc[1][0] = fmaf(v1, b.x, acc[1][0]);
        acc[1][1] = fmaf(v1, b.y, acc[1][1]);
        acc[1][2] = fmaf(v1, b.z, acc[1][2]);
        acc[1][3] = fmaf(v1, b.w, acc[1][3]);

        acc[2][0] = fmaf(v2, b.x, acc[2][0]);
        acc[2][1] = fmaf(v2, b.y, acc[2][1]);
        acc[2][2] = fmaf(v2, b.z, acc[2][2]);
        acc[2][3] = fmaf(v2, b.w, acc[2][3]);

        acc[3][0] = fmaf(v3, b.x, acc[3][0]);
        acc[3][1] = fmaf(v3, b.y, acc[3][1]);
        acc[3][2] = fmaf(v3, b.z, acc[3][2]);
        acc[3][3] = fmaf(v3, b.w, acc[3][3]);
    }

#pragma unroll
    for (int r = 0; r < 4; r++) {
        float4 v = make_float4(acc[r][0], acc[r][1], acc[r][2], acc[r][3]);
        *reinterpret_cast<float4*>(C + (ty + r) * LDM + tx) = v;
    }
}

__global__ __launch_bounds__(NTH, 2)
void ppb_kernel(const float* __restrict__ adj, float* __restrict__ out)
{
    extern __shared__ float sm[];
    float* xs = sm;                 // current x
    float* sc = xs + MATF;          // scores = threshold(adj, 0.5)
    float* b0 = sc + MATF;          // ping-pong matrix buffers
    float* b1 = b0 + MATF;
    float* b2 = b1 + MATF;
    float* b3 = b2 + MATF;
    float* red = b3 + MATF;         // NTH floats, reduction scratch
    float* alphaS = red + NTH;      // 1 float

    const int tid = threadIdx.x;
    const int bidx = blockIdx.x;
    const float* Ain = adj + (size_t)bidx * 4096;

    // Load adj -> xs, compute scores.
    for (int e = tid; e < 4096; e += NTH) {
        const int i = e >> 6, j = e & 63;
        const float v = Ain[e];
        xs[i * LDM + j] = v;
        sc[i * LDM + j] = (v > 0.5f) ? v : 0.0f;
    }
    if (tid == 0) *alphaS = 0.0f;
    __syncthreads();

    const float INV64  = 1.0f / 64.0f;
    const float SHRINK = 0.002f * 0.01f;   // REG_SP * STEP_PRI

    for (int it = 0; it < 50; it++) {
        const float alpha = *alphaS;
        const bool need_poly = (alpha != 0.0f);   // iter 0: grad term is exactly 0
        const float* poly = b2;

        if (need_poly) {
            // m0 = I + (x*x)/64 in b0; result starts as I@m0 == m0 (copy) in b2.
            for (int e = tid; e < 4096; e += NTH) {
                const int i = e >> 6, j = e & 63;
                const float v = xs[i * LDM + j];
                const float mv = v * v * INV64 + ((i == j) ? 1.0f : 0.0f);
                b0[i * LDM + j] = mv;
                b2[i * LDM + j] = mv;
            }
            __syncthreads();

            // exponentiation by squaring, p = 63, matching the reference order:
            // 5 rounds of {m = m@m; result = result@m}
            float* m  = b0; float* mt = b1;
            float* r  = b2; float* rt = b3;
#pragma unroll 1
            for (int rd = 0; rd < 5; rd++) {
                mm64(mt, m, m, tid);
                __syncthreads();
                { float* t = m; m = mt; mt = t; }
                mm64(rt, r, m, tid);
                __syncthreads();
                { float* t = r; r = rt; rt = t; }
            }
            poly = r;   // (I + x*x/64)^63
        }

        // x update: grad = -scores + 2*alpha*x*poly^T/64 ; soft-threshold; clamp <= 1.
        // Each thread reads/writes only its own xs elements; poly is read-only here.
        for (int e = tid; e < 4096; e += NTH) {
            const int i = e >> 6, j = e & 63;
            float x = xs[i * LDM + j];
            float g = -sc[i * LDM + j];
            if (need_poly)
                g += ((2.0f * alpha) * x) * poly[j * LDM + i] * INV64;
            const float til = x - 0.01f * g;
            float nx = fabsf(til) - SHRINK;
            nx = fmaxf(nx, 0.0f);
            x = 1.0f - fmaxf(1.0f - nx, 0.0f);
            xs[i * LDM + j] = x;
        }
        __syncthreads();

        // h = trace((I + x*x/64)^30)/64 - 1 with the new x.
        // Power-30 chain: m2, m4, m6=m2@m4, m8, m14=m6@m8, m16; trace(m14@m16) as a dot.
        for (int e = tid; e < 4096; e += NTH) {
            const int i = e >> 6, j = e & 63;
            const float v = xs[i * LDM + j];
            b0[i * LDM + j] = v * v * INV64 + ((i == j) ? 1.0f : 0.0f);
        }
        __syncthreads();
        mm64(b1, b0, b0, tid); __syncthreads();   // b1 = m^2
        mm64(b2, b1, b1, tid); __syncthreads();   // b2 = m^4
        mm64(b3, b1, b2, tid); __syncthreads();   // b3 = m^6  = m^2 @ m^4
        mm64(b0, b2, b2, tid); __syncthreads();   // b0 = m^8  (m^1 dead)
        mm64(b1, b3, b0, tid); __syncthreads();   // b1 = m^14 = m^6 @ m^8 (m^2 dead)
        mm64(b2, b0, b0, tid); __syncthreads();   // b2 = m^16 = m^8 @ m^8 (m^4 dead)

        // trace(m^30) = sum_{i,k} m14[i,k] * m16[k,i]
        float part = 0.0f;
        for (int e = tid; e < 4096; e += NTH) {
            const int i = e >> 6, k = e & 63;
            part += b1[i * LDM + k] * b2[k * LDM + i];
        }
        red[tid] = part;
        __syncthreads();
#pragma unroll
        for (int s = NTH / 2; s > 0; s >>= 1) {
            if (tid < s) red[tid] += red[tid + s];
            __syncthreads();
        }
        if (tid == 0) {
            const float h = red[0] * INV64 - 1.0f;
            *alphaS += 0.01f * h;
        }
        __syncthreads();
    }

    // output = threshold(x, 0.5)
    for (int e = tid; e < 4096; e += NTH) {
        const int i = e >> 6, j = e & 63;
        const float x = xs[i * LDM + j];
        out[(size_t)bidx * 4096 + e] = (x > 0.5f) ? x : 0.0f;
    }
}

extern "C" void kernel_launch(void* const* d_in, const int* in_sizes, int n_in,
                              void* d_out, int out_size)
{
    const float* adj = (const float*)d_in[0];
    float* out = (float*)d_out;

    const int batches = in_sizes[0] >> 12;   // elements / 4096
    const size_t smem = (size_t)(6 * MATF + NTH + 4) * sizeof(float);

    cudaFuncSetAttribute(ppb_kernel, cudaFuncAttributeMaxDynamicSharedMemorySize, (int)smem);
    ppb_kernel<<<batches, NTH, smem>>>(adj, out);
}